// round 2
// baseline (speedup 1.0000x reference)
#include <cuda_runtime.h>
#include <cuda_fp16.h>
#include <cstdint>

// Problem constants
constexpr int B_ = 16, T_ = 128, N_ = 64, D_ = 256, H_ = 512;
constexpr int MROWS = B_ * T_ * N_;      // 131072 flattened rows
constexpr int BT   = B_ * T_;            // 2048 attention problems
constexpr size_t BUF = (size_t)MROWS * H_;  // 64M elements per buffer

// ---------------- scratch: ONE fp16 device array, 6 buffers = 768 MB -------
// Layout: [q1, k1, v1, q2, k2, v2]. a1 aliases v1, a2 aliases v2, h aliases q1.
__device__ __half g_scratch[6 * BUF];

__device__ __forceinline__ uint32_t f2tf32(float x) {
    uint32_t r;
    asm("cvt.rna.tf32.f32 %0, %1;" : "=r"(r) : "f"(x));
    return r;
}

// load 4 consecutive elements, convert to tf32 bit patterns
__device__ __forceinline__ void ld4_tf32(const float* p, uint32_t* d) {
    const float4 v = *reinterpret_cast<const float4*>(p);
    d[0] = f2tf32(v.x); d[1] = f2tf32(v.y); d[2] = f2tf32(v.z); d[3] = f2tf32(v.w);
}
__device__ __forceinline__ void ld4_tf32(const __half* p, uint32_t* d) {
    __half2 h2[2];
    *reinterpret_cast<uint2*>(h2) = *reinterpret_cast<const uint2*>(p);
    d[0] = f2tf32(__low2float(h2[0])); d[1] = f2tf32(__high2float(h2[0]));
    d[2] = f2tf32(__low2float(h2[1])); d[3] = f2tf32(__high2float(h2[1]));
}

// store a pair of fp32 values as the destination type
__device__ __forceinline__ void st2(float* p, float v0, float v1) {
    *reinterpret_cast<float2*>(p) = make_float2(v0, v1);
}
__device__ __forceinline__ void st2(__half* p, float v0, float v1) {
    *reinterpret_cast<__half2*>(p) = __floats2half2_rn(v0, v1);
}

// mma.sync m16n8k8 tf32, D += A*B (D aliases C)
__device__ __forceinline__ void mma8(float* d, const uint32_t* a, const uint32_t* b) {
    asm volatile(
        "mma.sync.aligned.m16n8k8.row.col.f32.tf32.tf32.f32 "
        "{%0,%1,%2,%3}, {%4,%5,%6,%7}, {%8,%9}, {%0,%1,%2,%3};"
        : "+f"(d[0]), "+f"(d[1]), "+f"(d[2]), "+f"(d[3])
        : "r"(a[0]), "r"(a[1]), "r"(a[2]), "r"(a[3]),
          "r"(b[0]), "r"(b[1]));
}

// =============================== GEMM =====================================
// C[M,N] = act( alpha * (A @ B) + bias )
// A row-major [M,K] (optionally K-split across A0/A1, each with ld = lda),
// B row-major [K,N] fp32. Tiles: 128x128x32, 256 threads, 8 warps (4m x 2n),
// warp tile 32x64 via 2x8 m16n8k8 tf32 mma.
constexpr int BMT = 128, BNT = 128, BKT = 32;
constexpr int ALD = BKT + 4;   // 36
constexpr int BLD = BNT + 8;   // 136

template<typename TA, typename TC, bool RELU, bool SPLITA>
__global__ void __launch_bounds__(256) gemm_tf32(
    const TA* __restrict__ A0, const TA* __restrict__ A1,
    const float* __restrict__ Bm, const float* __restrict__ bias,
    TC* __restrict__ C, int M, int N, int K, int ksplit, int lda, float alpha)
{
    __shared__ uint32_t As[BMT * ALD];
    __shared__ uint32_t Bs[BKT * BLD];

    const int tid  = threadIdx.x;
    const int bm   = blockIdx.y * BMT;
    const int bn   = blockIdx.x * BNT;
    const int w    = tid >> 5, lane = tid & 31;
    const int wm   = (w & 3) * 32;
    const int wn   = (w >> 2) * 64;
    const int lr   = lane >> 2, lc = lane & 3;

    float acc[2][8][4];
#pragma unroll
    for (int i = 0; i < 2; i++)
#pragma unroll
        for (int j = 0; j < 8; j++)
#pragma unroll
            for (int k = 0; k < 4; k++) acc[i][j][k] = 0.f;

    for (int k0 = 0; k0 < K; k0 += BKT) {
        const TA* Abase = A0;
        int kl = k0;
        if (SPLITA && k0 >= ksplit) { Abase = A1; kl = k0 - ksplit; }

        // load A tile [128 x 32]
#pragma unroll
        for (int i = 0; i < 4; i++) {
            int id = tid + i * 256;
            int r = id >> 3, cq = (id & 7) << 2;
            ld4_tf32(Abase + (size_t)(bm + r) * lda + kl + cq, &As[r * ALD + cq]);
        }
        // load B tile [32 x 128]
#pragma unroll
        for (int i = 0; i < 4; i++) {
            int id = tid + i * 256;
            int r = id >> 5, cq = (id & 31) << 2;
            ld4_tf32(Bm + (size_t)(k0 + r) * N + bn + cq, &Bs[r * BLD + cq]);
        }
        __syncthreads();

#pragma unroll
        for (int kk = 0; kk < BKT; kk += 8) {
            uint32_t af[2][4];
#pragma unroll
            for (int mi = 0; mi < 2; mi++) {
                int r0 = wm + mi * 16 + lr;
                af[mi][0] = As[r0 * ALD + kk + lc];
                af[mi][1] = As[(r0 + 8) * ALD + kk + lc];
                af[mi][2] = As[r0 * ALD + kk + lc + 4];
                af[mi][3] = As[(r0 + 8) * ALD + kk + lc + 4];
            }
            uint32_t bf[8][2];
#pragma unroll
            for (int ni = 0; ni < 8; ni++) {
                int c0 = wn + ni * 8 + lr;
                bf[ni][0] = Bs[(kk + lc) * BLD + c0];
                bf[ni][1] = Bs[(kk + lc + 4) * BLD + c0];
            }
#pragma unroll
            for (int mi = 0; mi < 2; mi++)
#pragma unroll
                for (int ni = 0; ni < 8; ni++)
                    mma8(acc[mi][ni], af[mi], bf[ni]);
        }
        __syncthreads();
    }

    // epilogue
#pragma unroll
    for (int mi = 0; mi < 2; mi++) {
#pragma unroll
        for (int ni = 0; ni < 8; ni++) {
            int row = bm + wm + mi * 16 + lr;
            int col = bn + wn + ni * 8 + lc * 2;
            float b0 = 0.f, b1 = 0.f;
            if (bias) { b0 = bias[col]; b1 = bias[col + 1]; }
            float v0 = acc[mi][ni][0] * alpha + b0;
            float v1 = acc[mi][ni][1] * alpha + b1;
            float v2 = acc[mi][ni][2] * alpha + b0;
            float v3 = acc[mi][ni][3] * alpha + b1;
            if (RELU) {
                v0 = fmaxf(v0, 0.f); v1 = fmaxf(v1, 0.f);
                v2 = fmaxf(v2, 0.f); v3 = fmaxf(v3, 0.f);
            }
            st2(C + (size_t)row * N + col, v0, v1);
            st2(C + (size_t)(row + 8) * N + col, v2, v3);
        }
    }
}

// ============================ Attention ===================================
// One CTA per (b,t). S[64,64] = Q@K^T (Q pre-scaled), row softmax (fp32),
// O[64,512] = P@V. O may alias V (chunk reads complete before chunk writes).
constexpr int SLD = 68;

__global__ void __launch_bounds__(256) attn_kernel(
    const __half* __restrict__ Q, const __half* __restrict__ Kx,
    const __half* __restrict__ V, __half* __restrict__ O)
{
    __shared__ uint32_t bufA[64 * SLD];  // Q chunk, then V chunk
    __shared__ uint32_t bufB[64 * SLD];  // K chunk, then S / P

    const int tid = threadIdx.x, w = tid >> 5, lane = tid & 31;
    const int lr = lane >> 2, lc = lane & 3;
    const int wm = (w & 3) * 16;
    const int wn = (w >> 2) * 32;
    const size_t base = (size_t)blockIdx.x * (64 * 512);

    float sacc[4][4];
#pragma unroll
    for (int i = 0; i < 4; i++)
#pragma unroll
        for (int j = 0; j < 4; j++) sacc[i][j] = 0.f;

    // ---- Phase 1: S = Q @ K^T, contraction over H in chunks of 64 ----
    for (int hc = 0; hc < 512; hc += 64) {
#pragma unroll
        for (int i = 0; i < 4; i++) {
            int id = tid + i * 256;
            int r = id >> 4, cq = (id & 15) << 2;
            ld4_tf32(Q  + base + (size_t)r * 512 + hc + cq, &bufA[r * SLD + cq]);
            ld4_tf32(Kx + base + (size_t)r * 512 + hc + cq, &bufB[r * SLD + cq]);
        }
        __syncthreads();
#pragma unroll
        for (int kk = 0; kk < 64; kk += 8) {
            uint32_t af[4];
            int r0 = wm + lr;
            af[0] = bufA[r0 * SLD + kk + lc];
            af[1] = bufA[(r0 + 8) * SLD + kk + lc];
            af[2] = bufA[r0 * SLD + kk + lc + 4];
            af[3] = bufA[(r0 + 8) * SLD + kk + lc + 4];
#pragma unroll
            for (int ni = 0; ni < 4; ni++) {
                int c0 = wn + ni * 8 + lr;
                uint32_t bf[2] = { bufB[c0 * SLD + kk + lc],
                                   bufB[c0 * SLD + kk + lc + 4] };
                mma8(sacc[ni], af, bf);
            }
        }
        __syncthreads();
    }

    // ---- dump S (fp32) into bufB ----
    float* S = reinterpret_cast<float*>(bufB);
#pragma unroll
    for (int ni = 0; ni < 4; ni++) {
        int row = wm + lr, col = wn + ni * 8 + lc * 2;
        S[row * SLD + col]           = sacc[ni][0];
        S[row * SLD + col + 1]       = sacc[ni][1];
        S[(row + 8) * SLD + col]     = sacc[ni][2];
        S[(row + 8) * SLD + col + 1] = sacc[ni][3];
    }
    __syncthreads();

    // ---- Phase 2: softmax (fp32), each warp owns 8 rows ----
    uint32_t* P = bufB;
    for (int r = w * 8; r < w * 8 + 8; r++) {
        float v0 = S[r * SLD + lane], v1 = S[r * SLD + 32 + lane];
        float m = fmaxf(v0, v1);
#pragma unroll
        for (int o = 16; o > 0; o >>= 1) m = fmaxf(m, __shfl_xor_sync(0xffffffffu, m, o));
        float e0 = __expf(v0 - m), e1 = __expf(v1 - m);
        float s = e0 + e1;
#pragma unroll
        for (int o = 16; o > 0; o >>= 1) s += __shfl_xor_sync(0xffffffffu, s, o);
        float inv = 1.f / s;
        P[r * SLD + lane]      = f2tf32(e0 * inv);
        P[r * SLD + 32 + lane] = f2tf32(e1 * inv);
    }
    __syncthreads();

    // ---- Phase 3: O = P @ V, output chunks of 64 over H ----
    for (int hc = 0; hc < 512; hc += 64) {
#pragma unroll
        for (int i = 0; i < 4; i++) {
            int id = tid + i * 256;
            int r = id >> 4, cq = (id & 15) << 2;
            ld4_tf32(V + base + (size_t)r * 512 + hc + cq, &bufA[r * SLD + cq]);
        }
        __syncthreads();

        float oacc[4][4];
#pragma unroll
        for (int i = 0; i < 4; i++)
#pragma unroll
            for (int j = 0; j < 4; j++) oacc[i][j] = 0.f;

#pragma unroll
        for (int kk = 0; kk < 64; kk += 8) {
            uint32_t af[4];
            int r0 = wm + lr;
            af[0] = P[r0 * SLD + kk + lc];
            af[1] = P[(r0 + 8) * SLD + kk + lc];
            af[2] = P[r0 * SLD + kk + lc + 4];
            af[3] = P[(r0 + 8) * SLD + kk + lc + 4];
#pragma unroll
            for (int ni = 0; ni < 4; ni++) {
                int c0 = wn + ni * 8 + lr;
                uint32_t bf[2] = { bufA[(kk + lc) * SLD + c0],
                                   bufA[(kk + lc + 4) * SLD + c0] };
                mma8(oacc[ni], af, bf);
            }
        }
#pragma unroll
        for (int ni = 0; ni < 4; ni++) {
            int row = wm + lr, col = wn + ni * 8 + lc * 2;
            st2(O + base + (size_t)row * 512 + hc + col,       oacc[ni][0], oacc[ni][1]);
            st2(O + base + (size_t)(row + 8) * 512 + hc + col, oacc[ni][2], oacc[ni][3]);
        }
        __syncthreads();
    }
}

// ============================== launch ====================================
extern "C" void kernel_launch(void* const* d_in, const int* in_sizes, int n_in,
                              void* d_out, int out_size)
{
    const float* x1  = (const float*)d_in[0];
    const float* x2  = (const float*)d_in[1];
    const float* Wq1 = (const float*)d_in[2];
    const float* Wk1 = (const float*)d_in[3];
    const float* Wv1 = (const float*)d_in[4];
    const float* Wq2 = (const float*)d_in[5];
    const float* Wk2 = (const float*)d_in[6];
    const float* Wv2 = (const float*)d_in[7];
    const float* W1  = (const float*)d_in[8];
    const float* b1  = (const float*)d_in[9];
    const float* W2  = (const float*)d_in[10];
    const float* b2  = (const float*)d_in[11];
    float* out = (float*)d_out;

    __half* s;
    cudaGetSymbolAddress((void**)&s, g_scratch);
    __half* q1 = s + 0 * BUF;
    __half* k1 = s + 1 * BUF;
    __half* v1 = s + 2 * BUF;
    __half* q2 = s + 3 * BUF;
    __half* k2 = s + 4 * BUF;
    __half* v2 = s + 5 * BUF;
    __half* a1 = v1;  // attention output aliases V (safe, see attn_kernel)
    __half* a2 = v2;
    __half* h  = q1;  // MLP hidden reuses q1 (dead after attention)

    const float scale = 0.0625f;  // 256^-0.5
    dim3 blk(256);
    dim3 gproj(H_ / BNT, MROWS / BMT);  // (4, 1024)

    // Stage 1: projections (q pre-scaled)
    gemm_tf32<float, __half, false, false><<<gproj, blk>>>(x1, nullptr, Wq1, nullptr, q1, MROWS, H_, D_, 0, D_, scale);
    gemm_tf32<float, __half, false, false><<<gproj, blk>>>(x1, nullptr, Wk1, nullptr, k1, MROWS, H_, D_, 0, D_, 1.f);
    gemm_tf32<float, __half, false, false><<<gproj, blk>>>(x1, nullptr, Wv1, nullptr, v1, MROWS, H_, D_, 0, D_, 1.f);
    gemm_tf32<float, __half, false, false><<<gproj, blk>>>(x2, nullptr, Wq2, nullptr, q2, MROWS, H_, D_, 0, D_, scale);
    gemm_tf32<float, __half, false, false><<<gproj, blk>>>(x2, nullptr, Wk2, nullptr, k2, MROWS, H_, D_, 0, D_, 1.f);
    gemm_tf32<float, __half, false, false><<<gproj, blk>>>(x2, nullptr, Wv2, nullptr, v2, MROWS, H_, D_, 0, D_, 1.f);

    // Stage 2: cross attentions (q1 over k2 aggregating v1; q2 over k1 aggregating v2)
    attn_kernel<<<BT, blk>>>(q1, k2, v1, a1);
    attn_kernel<<<BT, blk>>>(q2, k1, v2, a2);

    // Stage 3: MLP. h = relu([a1|a2] @ W1 + b1); out = h @ W2 + b2
    gemm_tf32<__half, __half, true, true><<<gproj, blk>>>(a1, a2, W1, b1, h, MROWS, H_, 2 * H_, H_, H_, 1.f);
    gemm_tf32<__half, float, false, false><<<gproj, blk>>>(h, nullptr, W2, b2, out, MROWS, H_, H_, 0, H_, 1.f);
}

// round 3
// speedup vs baseline: 1.3271x; 1.3271x over previous
#include <cuda_runtime.h>
#include <cuda_fp16.h>
#include <cstdint>

// Problem constants
constexpr int B_ = 16, T_ = 128, N_ = 64, D_ = 256, H_ = 512;
constexpr int MROWS = B_ * T_ * N_;      // 131072 flattened rows
constexpr int BT   = B_ * T_;            // 2048 attention problems
constexpr size_t BUF = (size_t)MROWS * H_;  // 64M elements per buffer

// ---------------- scratch: ONE fp16 device array, 6 buffers = 768 MB -------
// Layout: [q1, k1, v1, q2, k2, v2]. a1 aliases v1, a2 aliases v2, h aliases q1.
__device__ __half g_scratch[6 * BUF];

// pack two fp32 -> one u32 of fp16x2
__device__ __forceinline__ uint32_t pk(float a, float b) {
    __half2 h = __floats2half2_rn(a, b);
    return *reinterpret_cast<uint32_t*>(&h);
}

// load 4 consecutive elems (k-direction), return 2 packed fp16x2 words
__device__ __forceinline__ uint2 ld4pk(const float* p) {
    const float4 v = *reinterpret_cast<const float4*>(p);
    return make_uint2(pk(v.x, v.y), pk(v.z, v.w));
}
__device__ __forceinline__ uint2 ld4pk(const __half* p) {
    return *reinterpret_cast<const uint2*>(p);  // already fp16 pairs
}

// store a pair of fp32 values as the destination type
__device__ __forceinline__ void st2(float* p, float v0, float v1) {
    *reinterpret_cast<float2*>(p) = make_float2(v0, v1);
}
__device__ __forceinline__ void st2(__half* p, float v0, float v1) {
    *reinterpret_cast<__half2*>(p) = __floats2half2_rn(v0, v1);
}

// mma.sync m16n8k16 fp16 in / fp32 accum, D += A*B (D aliases C)
__device__ __forceinline__ void mma16(float* d, const uint32_t* a, const uint32_t* b) {
    asm volatile(
        "mma.sync.aligned.m16n8k16.row.col.f32.f16.f16.f32 "
        "{%0,%1,%2,%3}, {%4,%5,%6,%7}, {%8,%9}, {%0,%1,%2,%3};"
        : "+f"(d[0]), "+f"(d[1]), "+f"(d[2]), "+f"(d[3])
        : "r"(a[0]), "r"(a[1]), "r"(a[2]), "r"(a[3]),
          "r"(b[0]), "r"(b[1]));
}

// =============================== GEMM =====================================
// C[M,N] = act( alpha * (A @ B) + bias ), fp16 MMA, fp32 accumulate.
// A row-major [M,K] fp32 or fp16 (optionally K-split across A0/A1).
// B row-major [K,N] fp32 (weights).
// Tiles: 128x128x32, 256 threads, 8 warps (4m x 2n), warp tile 32x64.
// smem word layouts (u32 = fp16x2 along k):
//   As[row][kp], stride 36  (36 % 32 == 4  -> A-frag loads conflict-free)
//   Bs[kp][n],  stride 136  (136 % 32 == 8 -> B-frag loads conflict-free)
constexpr int BMT = 128, BNT = 128, BKT = 32;
constexpr int AW = 36;    // >=16 words (32 k), %32==4
constexpr int BW = 136;   // >=128 words, %32==8

template<typename TA, typename TC, bool RELU, bool SPLITA>
__global__ void __launch_bounds__(256) gemm_h(
    const TA* __restrict__ A0, const TA* __restrict__ A1,
    const float* __restrict__ Bm, const float* __restrict__ bias,
    TC* __restrict__ C, int M, int N, int K, int ksplit, int lda, float alpha)
{
    __shared__ uint32_t As[BMT * AW];        // 18.4 KB
    __shared__ uint32_t Bs[(BKT / 2) * BW];  // 8.7 KB

    const int tid  = threadIdx.x;
    const int bm   = blockIdx.y * BMT;
    const int bn   = blockIdx.x * BNT;
    const int w    = tid >> 5, lane = tid & 31;
    const int wm   = (w & 3) * 32;
    const int wn   = (w >> 2) * 64;
    const int lr   = lane >> 2, lc = lane & 3;

    float acc[2][8][4];
#pragma unroll
    for (int i = 0; i < 2; i++)
#pragma unroll
        for (int j = 0; j < 8; j++)
#pragma unroll
            for (int k = 0; k < 4; k++) acc[i][j][k] = 0.f;

    for (int k0 = 0; k0 < K; k0 += BKT) {
        const TA* Abase = A0;
        int kl = k0;
        if (SPLITA && k0 >= ksplit) { Abase = A1; kl = k0 - ksplit; }

        // ---- A tile [128 rows x 32 k] -> packed words [row][kp0..15] ----
#pragma unroll
        for (int i = 0; i < 4; i++) {
            int id = tid + i * 256;
            int r = id >> 3, q = id & 7;               // q: which group of 4 k
            uint2 wv = ld4pk(Abase + (size_t)(bm + r) * lda + kl + q * 4);
            *reinterpret_cast<uint2*>(&As[r * AW + q * 2]) = wv;
        }
        // ---- B tile [32 k x 128 n] -> packed words [kp][n] ----
#pragma unroll
        for (int i = 0; i < 2; i++) {
            int id = tid + i * 256;
            int kp = id >> 5, n4 = (id & 31) * 4;
            const float4 va = *reinterpret_cast<const float4*>(
                Bm + (size_t)(k0 + 2 * kp) * N + bn + n4);
            const float4 vb = *reinterpret_cast<const float4*>(
                Bm + (size_t)(k0 + 2 * kp + 1) * N + bn + n4);
            uint4 wv = make_uint4(pk(va.x, vb.x), pk(va.y, vb.y),
                                  pk(va.z, vb.z), pk(va.w, vb.w));
            *reinterpret_cast<uint4*>(&Bs[kp * BW + n4]) = wv;
        }
        __syncthreads();

#pragma unroll
        for (int kk2 = 0; kk2 < BKT / 2; kk2 += 8) {   // two k16 chunks
            uint32_t af[2][4];
#pragma unroll
            for (int mi = 0; mi < 2; mi++) {
                int r0 = wm + mi * 16 + lr;
                af[mi][0] = As[r0 * AW + kk2 + lc];
                af[mi][1] = As[(r0 + 8) * AW + kk2 + lc];
                af[mi][2] = As[r0 * AW + kk2 + lc + 4];
                af[mi][3] = As[(r0 + 8) * AW + kk2 + lc + 4];
            }
            uint32_t bf[8][2];
#pragma unroll
            for (int ni = 0; ni < 8; ni++) {
                int c0 = wn + ni * 8 + lr;
                bf[ni][0] = Bs[(kk2 + lc) * BW + c0];
                bf[ni][1] = Bs[(kk2 + lc + 4) * BW + c0];
            }
#pragma unroll
            for (int mi = 0; mi < 2; mi++)
#pragma unroll
                for (int ni = 0; ni < 8; ni++)
                    mma16(acc[mi][ni], af[mi], bf[ni]);
        }
        __syncthreads();
    }

    // epilogue
#pragma unroll
    for (int mi = 0; mi < 2; mi++) {
#pragma unroll
        for (int ni = 0; ni < 8; ni++) {
            int row = bm + wm + mi * 16 + lr;
            int col = bn + wn + ni * 8 + lc * 2;
            float b0 = 0.f, b1 = 0.f;
            if (bias) { b0 = bias[col]; b1 = bias[col + 1]; }
            float v0 = acc[mi][ni][0] * alpha + b0;
            float v1 = acc[mi][ni][1] * alpha + b1;
            float v2 = acc[mi][ni][2] * alpha + b0;
            float v3 = acc[mi][ni][3] * alpha + b1;
            if (RELU) {
                v0 = fmaxf(v0, 0.f); v1 = fmaxf(v1, 0.f);
                v2 = fmaxf(v2, 0.f); v3 = fmaxf(v3, 0.f);
            }
            st2(C + (size_t)row * N + col, v0, v1);
            st2(C + (size_t)(row + 8) * N + col, v2, v3);
        }
    }
}

// ============================ Attention ===================================
// One CTA per (b,t). S[64,64] = Q@K^T (Q pre-scaled), fp32 softmax,
// O[64,512] = P@V. All operands fp16, fp32 accumulate. O may alias V.
// smem:
//   bufA: Q words [row][hp] stride 36, later P words [row][mp] stride 36
//   bufB: K words [row][hp] stride 36, later S fp32 [row][col] stride 68,
//         later V words [mp][h] stride 72 (72 % 32 == 8 -> conflict-free)
constexpr int QW = 36, SLD = 68, VW = 72;

__global__ void __launch_bounds__(256) attn_kernel(
    const __half* __restrict__ Q, const __half* __restrict__ Kx,
    const __half* __restrict__ V, __half* __restrict__ O)
{
    __shared__ uint32_t bufA[64 * QW];   // 9.2 KB
    __shared__ uint32_t bufB[64 * SLD];  // 17.4 KB (fits S fp32 and V words)

    const int tid = threadIdx.x, w = tid >> 5, lane = tid & 31;
    const int lr = lane >> 2, lc = lane & 3;
    const int wm = (w & 3) * 16;
    const int wn = (w >> 2) * 32;
    const size_t base = (size_t)blockIdx.x * (64 * 512);

    float sacc[4][4];
#pragma unroll
    for (int i = 0; i < 4; i++)
#pragma unroll
        for (int j = 0; j < 4; j++) sacc[i][j] = 0.f;

    // ---- Phase 1: S = Q @ K^T over H in chunks of 64 ----
    for (int hc = 0; hc < 512; hc += 64) {
#pragma unroll
        for (int i = 0; i < 4; i++) {
            int id = tid + i * 256;
            int r = id >> 4, q = id & 15;
            *reinterpret_cast<uint2*>(&bufA[r * QW + q * 2]) =
                ld4pk(Q + base + (size_t)r * 512 + hc + q * 4);
            *reinterpret_cast<uint2*>(&bufB[r * QW + q * 2]) =
                ld4pk(Kx + base + (size_t)r * 512 + hc + q * 4);
        }
        __syncthreads();
#pragma unroll
        for (int kk2 = 0; kk2 < 32; kk2 += 8) {    // 4 x k16
            uint32_t af[4];
            int r0 = wm + lr;
            af[0] = bufA[r0 * QW + kk2 + lc];
            af[1] = bufA[(r0 + 8) * QW + kk2 + lc];
            af[2] = bufA[r0 * QW + kk2 + lc + 4];
            af[3] = bufA[(r0 + 8) * QW + kk2 + lc + 4];
#pragma unroll
            for (int ni = 0; ni < 4; ni++) {
                int c0 = wn + ni * 8 + lr;
                uint32_t bf[2] = { bufB[c0 * QW + kk2 + lc],
                                   bufB[c0 * QW + kk2 + lc + 4] };
                mma16(sacc[ni], af, bf);
            }
        }
        __syncthreads();
    }

    // ---- dump S (fp32) into bufB ----
    float* S = reinterpret_cast<float*>(bufB);
#pragma unroll
    for (int ni = 0; ni < 4; ni++) {
        int row = wm + lr, col = wn + ni * 8 + lc * 2;
        S[row * SLD + col]           = sacc[ni][0];
        S[row * SLD + col + 1]       = sacc[ni][1];
        S[(row + 8) * SLD + col]     = sacc[ni][2];
        S[(row + 8) * SLD + col + 1] = sacc[ni][3];
    }
    __syncthreads();

    // ---- Phase 2: softmax (fp32), each warp owns 8 rows; write probs back --
    for (int r = w * 8; r < w * 8 + 8; r++) {
        float v0 = S[r * SLD + lane], v1 = S[r * SLD + 32 + lane];
        float m = fmaxf(v0, v1);
#pragma unroll
        for (int o = 16; o > 0; o >>= 1) m = fmaxf(m, __shfl_xor_sync(0xffffffffu, m, o));
        float e0 = __expf(v0 - m), e1 = __expf(v1 - m);
        float s = e0 + e1;
#pragma unroll
        for (int o = 16; o > 0; o >>= 1) s += __shfl_xor_sync(0xffffffffu, s, o);
        float inv = 1.f / s;
        S[r * SLD + lane]      = e0 * inv;
        S[r * SLD + 32 + lane] = e1 * inv;
    }
    __syncthreads();

    // ---- repack P into bufA as fp16 pair-words [row][mp] ----
    for (int idx = tid; idx < 64 * 32; idx += 256) {
        int row = idx >> 5, mp = idx & 31;
        bufA[row * QW + mp] = pk(S[row * SLD + 2 * mp], S[row * SLD + 2 * mp + 1]);
    }
    __syncthreads();

    // ---- hoist P fragments into registers (reused for all 8 h-chunks) ----
    uint32_t paf[4][4];
#pragma unroll
    for (int c = 0; c < 4; c++) {
        int kk2 = c * 8, r0 = wm + lr;
        paf[c][0] = bufA[r0 * QW + kk2 + lc];
        paf[c][1] = bufA[(r0 + 8) * QW + kk2 + lc];
        paf[c][2] = bufA[r0 * QW + kk2 + lc + 4];
        paf[c][3] = bufA[(r0 + 8) * QW + kk2 + lc + 4];
    }

    // ---- Phase 3: O = P @ V, output chunks of 64 over H ----
    for (int hc = 0; hc < 512; hc += 64) {
        __syncthreads();
        // V chunk [64 m x 64 h] -> packed words [mp][h] stride VW
#pragma unroll
        for (int i = 0; i < 2; i++) {
            int id = tid + i * 256;
            int mp = id >> 4, h4 = (id & 15) * 4;
            uint2 ra = *reinterpret_cast<const uint2*>(V + base + (size_t)(2 * mp) * 512 + hc + h4);
            uint2 rb = *reinterpret_cast<const uint2*>(V + base + (size_t)(2 * mp + 1) * 512 + hc + h4);
            uint4 wv = make_uint4(__byte_perm(ra.x, rb.x, 0x5410),
                                  __byte_perm(ra.x, rb.x, 0x7632),
                                  __byte_perm(ra.y, rb.y, 0x5410),
                                  __byte_perm(ra.y, rb.y, 0x7632));
            *reinterpret_cast<uint4*>(&bufB[mp * VW + h4]) = wv;
        }
        __syncthreads();

        float oacc[4][4];
#pragma unroll
        for (int i = 0; i < 4; i++)
#pragma unroll
            for (int j = 0; j < 4; j++) oacc[i][j] = 0.f;

#pragma unroll
        for (int c = 0; c < 4; c++) {
            int kk2 = c * 8;
#pragma unroll
            for (int ni = 0; ni < 4; ni++) {
                int c0 = wn + ni * 8 + lr;
                uint32_t bf[2] = { bufB[(kk2 + lc) * VW + c0],
                                   bufB[(kk2 + lc + 4) * VW + c0] };
                mma16(oacc[ni], paf[c], bf);
            }
        }
#pragma unroll
        for (int ni = 0; ni < 4; ni++) {
            int row = wm + lr, col = wn + ni * 8 + lc * 2;
            st2(O + base + (size_t)row * 512 + hc + col,       oacc[ni][0], oacc[ni][1]);
            st2(O + base + (size_t)(row + 8) * 512 + hc + col, oacc[ni][2], oacc[ni][3]);
        }
    }
}

// ============================== launch ====================================
extern "C" void kernel_launch(void* const* d_in, const int* in_sizes, int n_in,
                              void* d_out, int out_size)
{
    const float* x1  = (const float*)d_in[0];
    const float* x2  = (const float*)d_in[1];
    const float* Wq1 = (const float*)d_in[2];
    const float* Wk1 = (const float*)d_in[3];
    const float* Wv1 = (const float*)d_in[4];
    const float* Wq2 = (const float*)d_in[5];
    const float* Wk2 = (const float*)d_in[6];
    const float* Wv2 = (const float*)d_in[7];
    const float* W1  = (const float*)d_in[8];
    const float* b1  = (const float*)d_in[9];
    const float* W2  = (const float*)d_in[10];
    const float* b2  = (const float*)d_in[11];
    float* out = (float*)d_out;

    __half* s;
    cudaGetSymbolAddress((void**)&s, g_scratch);
    __half* q1 = s + 0 * BUF;
    __half* k1 = s + 1 * BUF;
    __half* v1 = s + 2 * BUF;
    __half* q2 = s + 3 * BUF;
    __half* k2 = s + 4 * BUF;
    __half* v2 = s + 5 * BUF;
    __half* a1 = v1;  // attention output aliases V (safe: per-chunk read-then-write)
    __half* a2 = v2;
    __half* h  = q1;  // MLP hidden reuses q1 (dead after attention)

    const float scale = 0.0625f;  // 256^-0.5
    dim3 blk(256);
    dim3 gproj(H_ / BNT, MROWS / BMT);  // (4, 1024)

    // Stage 1: projections (q pre-scaled)
    gemm_h<float, __half, false, false><<<gproj, blk>>>(x1, nullptr, Wq1, nullptr, q1, MROWS, H_, D_, 0, D_, scale);
    gemm_h<float, __half, false, false><<<gproj, blk>>>(x1, nullptr, Wk1, nullptr, k1, MROWS, H_, D_, 0, D_, 1.f);
    gemm_h<float, __half, false, false><<<gproj, blk>>>(x1, nullptr, Wv1, nullptr, v1, MROWS, H_, D_, 0, D_, 1.f);
    gemm_h<float, __half, false, false><<<gproj, blk>>>(x2, nullptr, Wq2, nullptr, q2, MROWS, H_, D_, 0, D_, scale);
    gemm_h<float, __half, false, false><<<gproj, blk>>>(x2, nullptr, Wk2, nullptr, k2, MROWS, H_, D_, 0, D_, 1.f);
    gemm_h<float, __half, false, false><<<gproj, blk>>>(x2, nullptr, Wv2, nullptr, v2, MROWS, H_, D_, 0, D_, 1.f);

    // Stage 2: cross attentions
    attn_kernel<<<BT, blk>>>(q1, k2, v1, a1);
    attn_kernel<<<BT, blk>>>(q2, k1, v2, a2);

    // Stage 3: MLP. h = relu([a1|a2] @ W1 + b1); out = h @ W2 + b2
    gemm_h<__half, __half, true, true><<<gproj, blk>>>(a1, a2, W1, b1, h, MROWS, H_, 2 * H_, H_, H_, 1.f);
    gemm_h<__half, float, false, false><<<gproj, blk>>>(h, nullptr, W2, b2, out, MROWS, H_, H_, 0, H_, 1.f);
}

// round 4
// speedup vs baseline: 1.8386x; 1.3854x over previous
#include <cuda_runtime.h>
#include <cuda_fp16.h>
#include <cstdint>

// Problem constants
constexpr int B_ = 16, T_ = 128, N_ = 64, D_ = 256, H_ = 512;
constexpr int MROWS = B_ * T_ * N_;          // 131072 flattened rows
constexpr int BT   = B_ * T_;                // 2048 attention problems
constexpr size_t BUF  = (size_t)MROWS * H_;  // 67.1M elems (q/k/v/a buffers)
constexpr size_t XBUF = (size_t)MROWS * D_;  // 33.5M elems (fp16 copies of x)

// ---------------- scratch (device globals) ---------------------------------
// g_h: [q1,k1,v1,q2,k2,v2] (6*BUF) + [xh1,xh2] (2*XBUF)  = ~939 MB
__device__ __align__(16) __half g_h[6 * BUF + 2 * XBUF];
// packed fp16x2 weights (k-pair words): wqkv1(3*128*512) wqkv2(3*128*512)
// w1p(512*512) w2p(256*512)  = 786432 words
__device__ __align__(16) uint32_t g_w[786432];

// pack two fp32 -> one u32 of fp16x2
__device__ __forceinline__ uint32_t pk(float a, float b) {
    __half2 h = __floats2half2_rn(a, b);
    return *reinterpret_cast<uint32_t*>(&h);
}
__device__ __forceinline__ void st2(float* p, float v0, float v1) {
    *reinterpret_cast<float2*>(p) = make_float2(v0, v1);
}
__device__ __forceinline__ void st2(__half* p, float v0, float v1) {
    *reinterpret_cast<__half2*>(p) = __floats2half2_rn(v0, v1);
}
__device__ __forceinline__ uint2 ld4pk(const __half* p) {
    return *reinterpret_cast<const uint2*>(p);
}

// mma.sync m16n8k16 fp16 in / fp32 accum, D += A*B
__device__ __forceinline__ void mma16(float* d, const uint32_t* a, const uint32_t* b) {
    asm volatile(
        "mma.sync.aligned.m16n8k16.row.col.f32.f16.f16.f32 "
        "{%0,%1,%2,%3}, {%4,%5,%6,%7}, {%8,%9}, {%0,%1,%2,%3};"
        : "+f"(d[0]), "+f"(d[1]), "+f"(d[2]), "+f"(d[3])
        : "r"(a[0]), "r"(a[1]), "r"(a[2]), "r"(a[3]),
          "r"(b[0]), "r"(b[1]));
}

// cp.async 16B global -> shared
__device__ __forceinline__ void cpa16(uint32_t dst_smem, const void* src) {
    asm volatile("cp.async.cg.shared.global [%0], [%1], 16;" :: "r"(dst_smem), "l"(src));
}
__device__ __forceinline__ void cpa_commit() { asm volatile("cp.async.commit_group;"); }
__device__ __forceinline__ void cpa_wait1()  { asm volatile("cp.async.wait_group 1;"); }

// ======================= conversion pre-pass ==============================
__global__ void cvt_f2h(const float* __restrict__ src, __half* __restrict__ dst, int n4) {
    for (int i = blockIdx.x * blockDim.x + threadIdx.x; i < n4; i += gridDim.x * blockDim.x) {
        float4 v = reinterpret_cast<const float4*>(src)[i];
        uint2 w = make_uint2(pk(v.x, v.y), pk(v.z, v.w));
        reinterpret_cast<uint2*>(dst)[i] = w;
    }
}
// W [K,512] fp32 -> out u32 [K/2][512], word = {W[2kp,n], W[2kp+1,n]}
__global__ void pack_w(const float* __restrict__ W, uint32_t* __restrict__ out, int K2) {
    int total = K2 * 512;
    for (int i = blockIdx.x * blockDim.x + threadIdx.x; i < total; i += gridDim.x * blockDim.x) {
        int kp = i >> 9, n = i & 511;
        out[i] = pk(W[(size_t)(2 * kp) * 512 + n], W[(size_t)(2 * kp + 1) * 512 + n]);
    }
}

// =============================== GEMM =====================================
// C[M,512] = act( alpha * (A @ B) + bias ).  A fp16 row-major [M,K]
// (optionally K-split A0/A1), B pre-packed u32 k-pair words [K/2][512].
// Tiles 128x128x64, 2-stage cp.async double buffer, 256 thr, 8 warps (4m x 2n).
// smem word layouts: As[row][kp] stride 36 (%32==4), Bs[kp][n] stride 136 (%32==8).
constexpr int AW = 36, BW = 136;
constexpr int A_ST = 128 * AW;            // 4608 words per stage
constexpr int B_ST = 32 * BW;             // 4352 words per stage
constexpr size_t GEMM_SMEM = (size_t)(A_ST + B_ST) * 2 * 4;  // 71680 B

template<typename TC, bool RELU, bool SPLITA>
__global__ void __launch_bounds__(256) gemm_p(
    const __half* __restrict__ A0, const __half* __restrict__ A1,
    const uint32_t* __restrict__ Bp, const float* __restrict__ bias,
    TC* __restrict__ C, int K, int ksplit, int lda,
    size_t bstride, size_t cstride, float alpha0)
{
    extern __shared__ uint32_t smem[];
    uint32_t* As = smem;
    uint32_t* Bs = smem + 2 * A_ST;
    const uint32_t as_base = (uint32_t)__cvta_generic_to_shared(As);
    const uint32_t bs_base = (uint32_t)__cvta_generic_to_shared(Bs);

    const int tid = threadIdx.x;
    const int bm  = blockIdx.y * 128;
    const int bn  = blockIdx.x * 128;
    const uint32_t* Bz = Bp + (size_t)blockIdx.z * bstride;
    TC* Cz = C + (size_t)blockIdx.z * cstride;
    const float alpha = (blockIdx.z == 0) ? alpha0 : 1.0f;

    const int w = tid >> 5, lane = tid & 31;
    const int wm = (w & 3) * 32, wn = (w >> 2) * 64;
    const int lr = lane >> 2, lc = lane & 3;

    // per-thread copy coords (4 chunks each for A and B)
    const int ar = tid >> 1, aq = (tid & 1) << 2;        // A: 2 thr/row, rows tid>>1 (+64 per i... recompute below)
    (void)ar; (void)aq;

    float acc[2][8][4];
#pragma unroll
    for (int i = 0; i < 2; i++)
#pragma unroll
        for (int j = 0; j < 8; j++)
#pragma unroll
            for (int k = 0; k < 4; k++) acc[i][j][k] = 0.f;

    auto load_stage = [&](int s, int k0) {
        const __half* Ab = A0;
        int kl = k0;
        if (SPLITA && k0 >= ksplit) { Ab = A1; kl = k0 - ksplit; }
        // A tile: 128 rows x 64 fp16 = 1024 x 16B chunks
#pragma unroll
        for (int i = 0; i < 4; i++) {
            int id = tid + i * 256;
            int r = id >> 3, q = id & 7;                  // q: 8 halves each
            cpa16(as_base + (uint32_t)(s * A_ST + r * AW + q * 4) * 4,
                  Ab + (size_t)(bm + r) * lda + kl + q * 8);
        }
        // B tile: 32 kp-rows x 128 words = 1024 x 16B chunks
#pragma unroll
        for (int i = 0; i < 4; i++) {
            int id = tid + i * 256;
            int kp = id >> 5, j = id & 31;
            cpa16(bs_base + (uint32_t)(s * B_ST + kp * BW + j * 4) * 4,
                  Bz + (size_t)((k0 >> 1) + kp) * 512 + bn + j * 4);
        }
    };

    const int ntiles = K >> 6;
    load_stage(0, 0);
    cpa_commit();

    for (int t = 0; t < ntiles; t++) {
        if (t + 1 < ntiles) load_stage((t + 1) & 1, (t + 1) << 6);
        cpa_commit();
        cpa_wait1();
        __syncthreads();

        const uint32_t* Ast = As + (t & 1) * A_ST;
        const uint32_t* Bst = Bs + (t & 1) * B_ST;
#pragma unroll
        for (int kk2 = 0; kk2 < 32; kk2 += 8) {
            uint32_t af[2][4];
#pragma unroll
            for (int mi = 0; mi < 2; mi++) {
                int r0 = wm + mi * 16 + lr;
                af[mi][0] = Ast[r0 * AW + kk2 + lc];
                af[mi][1] = Ast[(r0 + 8) * AW + kk2 + lc];
                af[mi][2] = Ast[r0 * AW + kk2 + lc + 4];
                af[mi][3] = Ast[(r0 + 8) * AW + kk2 + lc + 4];
            }
            uint32_t bf[8][2];
#pragma unroll
            for (int ni = 0; ni < 8; ni++) {
                int c0 = wn + ni * 8 + lr;
                bf[ni][0] = Bst[(kk2 + lc) * BW + c0];
                bf[ni][1] = Bst[(kk2 + lc + 4) * BW + c0];
            }
#pragma unroll
            for (int mi = 0; mi < 2; mi++)
#pragma unroll
                for (int ni = 0; ni < 8; ni++)
                    mma16(acc[mi][ni], af[mi], bf[ni]);
        }
        __syncthreads();
    }

    // epilogue (N fixed at 512)
#pragma unroll
    for (int mi = 0; mi < 2; mi++) {
#pragma unroll
        for (int ni = 0; ni < 8; ni++) {
            int row = bm + wm + mi * 16 + lr;
            int col = bn + wn + ni * 8 + lc * 2;
            float b0 = 0.f, b1 = 0.f;
            if (bias) { b0 = bias[col]; b1 = bias[col + 1]; }
            float v0 = acc[mi][ni][0] * alpha + b0;
            float v1 = acc[mi][ni][1] * alpha + b1;
            float v2 = acc[mi][ni][2] * alpha + b0;
            float v3 = acc[mi][ni][3] * alpha + b1;
            if (RELU) {
                v0 = fmaxf(v0, 0.f); v1 = fmaxf(v1, 0.f);
                v2 = fmaxf(v2, 0.f); v3 = fmaxf(v3, 0.f);
            }
            st2(Cz + (size_t)row * 512 + col, v0, v1);
            st2(Cz + (size_t)(row + 8) * 512 + col, v2, v3);
        }
    }
}

// ============================ Attention ===================================
// (unchanged from R3 — passing) One CTA per (b,t).
constexpr int QW = 36, SLD = 68, VW = 72;

__global__ void __launch_bounds__(256) attn_kernel(
    const __half* __restrict__ Q, const __half* __restrict__ Kx,
    const __half* __restrict__ V, __half* __restrict__ O)
{
    __shared__ uint32_t bufA[64 * QW];
    __shared__ uint32_t bufB[64 * SLD];

    const int tid = threadIdx.x, w = tid >> 5, lane = tid & 31;
    const int lr = lane >> 2, lc = lane & 3;
    const int wm = (w & 3) * 16;
    const int wn = (w >> 2) * 32;
    const size_t base = (size_t)blockIdx.x * (64 * 512);

    float sacc[4][4];
#pragma unroll
    for (int i = 0; i < 4; i++)
#pragma unroll
        for (int j = 0; j < 4; j++) sacc[i][j] = 0.f;

    for (int hc = 0; hc < 512; hc += 64) {
#pragma unroll
        for (int i = 0; i < 4; i++) {
            int id = tid + i * 256;
            int r = id >> 4, q = id & 15;
            *reinterpret_cast<uint2*>(&bufA[r * QW + q * 2]) =
                ld4pk(Q + base + (size_t)r * 512 + hc + q * 4);
            *reinterpret_cast<uint2*>(&bufB[r * QW + q * 2]) =
                ld4pk(Kx + base + (size_t)r * 512 + hc + q * 4);
        }
        __syncthreads();
#pragma unroll
        for (int kk2 = 0; kk2 < 32; kk2 += 8) {
            uint32_t af[4];
            int r0 = wm + lr;
            af[0] = bufA[r0 * QW + kk2 + lc];
            af[1] = bufA[(r0 + 8) * QW + kk2 + lc];
            af[2] = bufA[r0 * QW + kk2 + lc + 4];
            af[3] = bufA[(r0 + 8) * QW + kk2 + lc + 4];
#pragma unroll
            for (int ni = 0; ni < 4; ni++) {
                int c0 = wn + ni * 8 + lr;
                uint32_t bf[2] = { bufB[c0 * QW + kk2 + lc],
                                   bufB[c0 * QW + kk2 + lc + 4] };
                mma16(sacc[ni], af, bf);
            }
        }
        __syncthreads();
    }

    float* S = reinterpret_cast<float*>(bufB);
#pragma unroll
    for (int ni = 0; ni < 4; ni++) {
        int row = wm + lr, col = wn + ni * 8 + lc * 2;
        S[row * SLD + col]           = sacc[ni][0];
        S[row * SLD + col + 1]       = sacc[ni][1];
        S[(row + 8) * SLD + col]     = sacc[ni][2];
        S[(row + 8) * SLD + col + 1] = sacc[ni][3];
    }
    __syncthreads();

    for (int r = w * 8; r < w * 8 + 8; r++) {
        float v0 = S[r * SLD + lane], v1 = S[r * SLD + 32 + lane];
        float m = fmaxf(v0, v1);
#pragma unroll
        for (int o = 16; o > 0; o >>= 1) m = fmaxf(m, __shfl_xor_sync(0xffffffffu, m, o));
        float e0 = __expf(v0 - m), e1 = __expf(v1 - m);
        float s = e0 + e1;
#pragma unroll
        for (int o = 16; o > 0; o >>= 1) s += __shfl_xor_sync(0xffffffffu, s, o);
        float inv = 1.f / s;
        S[r * SLD + lane]      = e0 * inv;
        S[r * SLD + 32 + lane] = e1 * inv;
    }
    __syncthreads();

    for (int idx = tid; idx < 64 * 32; idx += 256) {
        int row = idx >> 5, mp = idx & 31;
        bufA[row * QW + mp] = pk(S[row * SLD + 2 * mp], S[row * SLD + 2 * mp + 1]);
    }
    __syncthreads();

    uint32_t paf[4][4];
#pragma unroll
    for (int c = 0; c < 4; c++) {
        int kk2 = c * 8, r0 = wm + lr;
        paf[c][0] = bufA[r0 * QW + kk2 + lc];
        paf[c][1] = bufA[(r0 + 8) * QW + kk2 + lc];
        paf[c][2] = bufA[r0 * QW + kk2 + lc + 4];
        paf[c][3] = bufA[(r0 + 8) * QW + kk2 + lc + 4];
    }

    for (int hc = 0; hc < 512; hc += 64) {
        __syncthreads();
#pragma unroll
        for (int i = 0; i < 2; i++) {
            int id = tid + i * 256;
            int mp = id >> 4, h4 = (id & 15) * 4;
            uint2 ra = *reinterpret_cast<const uint2*>(V + base + (size_t)(2 * mp) * 512 + hc + h4);
            uint2 rb = *reinterpret_cast<const uint2*>(V + base + (size_t)(2 * mp + 1) * 512 + hc + h4);
            uint4 wv = make_uint4(__byte_perm(ra.x, rb.x, 0x5410),
                                  __byte_perm(ra.x, rb.x, 0x7632),
                                  __byte_perm(ra.y, rb.y, 0x5410),
                                  __byte_perm(ra.y, rb.y, 0x7632));
            *reinterpret_cast<uint4*>(&bufB[mp * VW + h4]) = wv;
        }
        __syncthreads();

        float oacc[4][4];
#pragma unroll
        for (int i = 0; i < 4; i++)
#pragma unroll
            for (int j = 0; j < 4; j++) oacc[i][j] = 0.f;

#pragma unroll
        for (int c = 0; c < 4; c++) {
            int kk2 = c * 8;
#pragma unroll
            for (int ni = 0; ni < 4; ni++) {
                int c0 = wn + ni * 8 + lr;
                uint32_t bf[2] = { bufB[(kk2 + lc) * VW + c0],
                                   bufB[(kk2 + lc + 4) * VW + c0] };
                mma16(oacc[ni], paf[c], bf);
            }
        }
#pragma unroll
        for (int ni = 0; ni < 4; ni++) {
            int row = wm + lr, col = wn + ni * 8 + lc * 2;
            st2(O + base + (size_t)row * 512 + hc + col,       oacc[ni][0], oacc[ni][1]);
            st2(O + base + (size_t)(row + 8) * 512 + hc + col, oacc[ni][2], oacc[ni][3]);
        }
    }
}

// ============================== launch ====================================
extern "C" void kernel_launch(void* const* d_in, const int* in_sizes, int n_in,
                              void* d_out, int out_size)
{
    const float* x1  = (const float*)d_in[0];
    const float* x2  = (const float*)d_in[1];
    const float* Wq1 = (const float*)d_in[2];
    const float* Wk1 = (const float*)d_in[3];
    const float* Wv1 = (const float*)d_in[4];
    const float* Wq2 = (const float*)d_in[5];
    const float* Wk2 = (const float*)d_in[6];
    const float* Wv2 = (const float*)d_in[7];
    const float* W1  = (const float*)d_in[8];
    const float* b1  = (const float*)d_in[9];
    const float* W2  = (const float*)d_in[10];
    const float* b2  = (const float*)d_in[11];
    float* out = (float*)d_out;

    __half* s;  uint32_t* wbase;
    cudaGetSymbolAddress((void**)&s, g_h);
    cudaGetSymbolAddress((void**)&wbase, g_w);

    __half* q1 = s + 0 * BUF;
    __half* k1 = s + 1 * BUF;
    __half* v1 = s + 2 * BUF;
    __half* q2 = s + 3 * BUF;
    __half* k2 = s + 4 * BUF;
    __half* v2 = s + 5 * BUF;
    __half* xh1 = s + 6 * BUF;
    __half* xh2 = xh1 + XBUF;
    __half* a1 = v1;   // attention output aliases V (per-chunk read-then-write)
    __half* a2 = v2;
    __half* h  = q1;   // MLP hidden reuses q1

    constexpr size_t WSZ = 128 * 512;        // packed words per 256-K weight
    uint32_t* wqkv1 = wbase;                  // 3 * WSZ
    uint32_t* wqkv2 = wbase + 3 * WSZ;        // 3 * WSZ
    uint32_t* w1p   = wbase + 6 * WSZ;        // 512*512
    uint32_t* w2p   = w1p + 512 * 512;        // 256*512

    const float scale = 0.0625f;  // 256^-0.5
    dim3 blk(256);

    // smem opt-in for the pipelined GEMM instantiations (idempotent host calls)
    cudaFuncSetAttribute(gemm_p<__half, false, false>, cudaFuncAttributeMaxDynamicSharedMemorySize, (int)GEMM_SMEM);
    cudaFuncSetAttribute(gemm_p<__half, true,  true >, cudaFuncAttributeMaxDynamicSharedMemorySize, (int)GEMM_SMEM);
    cudaFuncSetAttribute(gemm_p<float,  false, false>, cudaFuncAttributeMaxDynamicSharedMemorySize, (int)GEMM_SMEM);

    // ---- pre-pass: fp16 copies of x, packed weights ----
    cvt_f2h<<<4096, 256>>>(x1, xh1, (int)(XBUF / 4));
    cvt_f2h<<<4096, 256>>>(x2, xh2, (int)(XBUF / 4));
    pack_w<<<256, 256>>>(Wq1, wqkv1 + 0 * WSZ, 128);
    pack_w<<<256, 256>>>(Wk1, wqkv1 + 1 * WSZ, 128);
    pack_w<<<256, 256>>>(Wv1, wqkv1 + 2 * WSZ, 128);
    pack_w<<<256, 256>>>(Wq2, wqkv2 + 0 * WSZ, 128);
    pack_w<<<256, 256>>>(Wk2, wqkv2 + 1 * WSZ, 128);
    pack_w<<<256, 256>>>(Wv2, wqkv2 + 2 * WSZ, 128);
    pack_w<<<512, 256>>>(W1, w1p, 512);
    pack_w<<<256, 256>>>(W2, w2p, 256);

    // ---- stage 1: fused projections (z -> {q,k,v}; q pre-scaled) ----
    dim3 gproj(4, MROWS / 128, 3);
    gemm_p<__half, false, false><<<gproj, blk, GEMM_SMEM>>>(
        xh1, nullptr, wqkv1, nullptr, q1, D_, 0, D_, WSZ, BUF, scale);
    gemm_p<__half, false, false><<<gproj, blk, GEMM_SMEM>>>(
        xh2, nullptr, wqkv2, nullptr, q2, D_, 0, D_, WSZ, BUF, scale);

    // ---- stage 2: cross attentions ----
    attn_kernel<<<BT, blk>>>(q1, k2, v1, a1);
    attn_kernel<<<BT, blk>>>(q2, k1, v2, a2);

    // ---- stage 3: MLP ----
    dim3 gmlp(4, MROWS / 128, 1);
    gemm_p<__half, true, true><<<gmlp, blk, GEMM_SMEM>>>(
        a1, a2, w1p, b1, h, 2 * H_, H_, H_, 0, 0, 1.f);
    gemm_p<float, false, false><<<gmlp, blk, GEMM_SMEM>>>(
        h, nullptr, w2p, b2, out, H_, 0, H_, 0, 0, 1.f);
}